// round 1
// baseline (speedup 1.0000x reference)
#include <cuda_runtime.h>

// 2-layer LSTM (HID=10) + linear head, B=2048, T=1024, future=64.
// One 16-lane group per batch element; lane j < 10 owns hidden unit j.
// All weights in registers; state broadcast via width-16 shuffles.

#define HID 10
#define T_FIXED 1024
#define FULLMASK 0xffffffffu

__device__ __forceinline__ float sigf(float v) {
    // sigmoid(v) = 1 / (1 + e^-v); __expf+__fdividef ~2ulp, fine for 1e-3
    return __fdividef(1.0f, 1.0f + __expf(-v));
}
__device__ __forceinline__ float tanh_fast(float v) {
    // tanh(v) = 2*sigmoid(2v) - 1
    return 2.0f * __fdividef(1.0f, 1.0f + __expf(-2.0f * v)) - 1.0f;
}

struct LSTMRegs {
    float wih1[4];        // W_ih1 rows (j,10+j,20+j,30+j), col 0
    float b1[4];          // b_ih1 + b_hh1
    float b2[4];          // b_ih2 + b_hh2
    float whh1[4][HID];
    float wih2[4][HID];
    float whh2[4][HID];
    float wlin;
    float blin;
};

// One full time step for both layers + linear head.
// Returns y (valid on ALL lanes of the 16-lane group).
__device__ __forceinline__ float lstm2_step(
    float xt, float& h1, float& c1, float& h2, float& c2,
    const LSTMRegs& R, int j)
{
    // ---- layer 1 gates: i,f,g,o ----
    float g0 = R.b1[0] + R.wih1[0] * xt;
    float g1 = R.b1[1] + R.wih1[1] * xt;
    float g2 = R.b1[2] + R.wih1[2] * xt;
    float g3 = R.b1[3] + R.wih1[3] * xt;
#pragma unroll
    for (int m = 0; m < HID; m++) {
        float hm = __shfl_sync(FULLMASK, h1, m, 16);
        g0 += R.whh1[0][m] * hm;
        g1 += R.whh1[1][m] * hm;
        g2 += R.whh1[2][m] * hm;
        g3 += R.whh1[3][m] * hm;
    }
    c1 = sigf(g1) * c1 + sigf(g0) * tanh_fast(g2);
    h1 = sigf(g3) * tanh_fast(c1);

    // ---- layer 2 gates ----
    float a0 = R.b2[0], a1 = R.b2[1], a2 = R.b2[2], a3 = R.b2[3];
#pragma unroll
    for (int m = 0; m < HID; m++) {
        float h1m = __shfl_sync(FULLMASK, h1, m, 16);
        float h2m = __shfl_sync(FULLMASK, h2, m, 16);
        a0 += R.wih2[0][m] * h1m + R.whh2[0][m] * h2m;
        a1 += R.wih2[1][m] * h1m + R.whh2[1][m] * h2m;
        a2 += R.wih2[2][m] * h1m + R.whh2[2][m] * h2m;
        a3 += R.wih2[3][m] * h1m + R.whh2[3][m] * h2m;
    }
    c2 = sigf(a1) * c2 + sigf(a0) * tanh_fast(a2);
    h2 = sigf(a3) * tanh_fast(c2);

    // ---- linear head: y = sum_j wlin[j]*h2[j] + blin, reduced over the group ----
    float p = (j < HID) ? R.wlin * h2 : 0.0f;
    p += __shfl_xor_sync(FULLMASK, p, 8, 16);
    p += __shfl_xor_sync(FULLMASK, p, 4, 16);
    p += __shfl_xor_sync(FULLMASK, p, 2, 16);
    p += __shfl_xor_sync(FULLMASK, p, 1, 16);
    return p + R.blin;
}

__global__ void lstm2_seq_kernel(
    const float* __restrict__ x,
    const float* __restrict__ W_ih1, const float* __restrict__ W_hh1,
    const float* __restrict__ b_ih1, const float* __restrict__ b_hh1,
    const float* __restrict__ W_ih2, const float* __restrict__ W_hh2,
    const float* __restrict__ b_ih2, const float* __restrict__ b_hh2,
    const float* __restrict__ W_lin, const float* __restrict__ b_lin,
    float* __restrict__ out,
    int B, int T, int outT)
{
    const int tid    = blockIdx.x * blockDim.x + threadIdx.x;
    const int warpId = tid >> 5;
    const int lane   = tid & 31;
    const int half   = lane >> 4;     // which batch within the warp
    const int j      = lane & 15;     // lane within the 16-lane group
    const int b      = warpId * 2 + half;

    const bool act = (j < HID) && (b < B);

    LSTMRegs R;
#pragma unroll
    for (int g = 0; g < 4; g++) {
        const int r = g * HID + j;    // gate row (only valid when act)
        R.wih1[g] = act ? W_ih1[r] : 0.0f;
        R.b1[g]   = act ? (b_ih1[r] + b_hh1[r]) : 0.0f;
        R.b2[g]   = act ? (b_ih2[r] + b_hh2[r]) : 0.0f;
#pragma unroll
        for (int m = 0; m < HID; m++) {
            R.whh1[g][m] = act ? W_hh1[r * HID + m] : 0.0f;
            R.wih2[g][m] = act ? W_ih2[r * HID + m] : 0.0f;
            R.whh2[g][m] = act ? W_hh2[r * HID + m] : 0.0f;
        }
    }
    R.wlin = act ? W_lin[j] : 0.0f;
    R.blin = b_lin[0];

    float h1 = 0.0f, c1 = 0.0f, h2 = 0.0f, c2 = 0.0f;
    float y = 0.0f, ybuf = 0.0f;

    const bool bvalid = (b < B);
    const float* xrow = x + (size_t)(bvalid ? b : 0) * T;
    float* orow = out + (size_t)(bvalid ? b : 0) * outT;

    // ---- main sequence: T steps, processed in chunks of 16 ----
    for (int t0 = 0; t0 < T; t0 += 16) {
        float xch = bvalid ? xrow[t0 + j] : 0.0f;  // coalesced 16-step chunk
#pragma unroll 1
        for (int tt = 0; tt < 16; tt++) {
            float xt = __shfl_sync(FULLMASK, xch, tt, 16);
            y = lstm2_step(xt, h1, c1, h2, c2, R, j);
            if (j == tt) ybuf = y;
        }
        if (bvalid) orow[t0 + j] = ybuf;           // coalesced store
    }

    // ---- future steps: feed y back as input ----
    for (int t0 = T; t0 < outT; t0 += 16) {
        const int nsteps = min(16, outT - t0);
#pragma unroll 1
        for (int tt = 0; tt < nsteps; tt++) {
            y = lstm2_step(y, h1, c1, h2, c2, R, j);
            if (j == tt) ybuf = y;
        }
        if (bvalid && j < nsteps) orow[t0 + j] = ybuf;
    }
}

extern "C" void kernel_launch(void* const* d_in, const int* in_sizes, int n_in,
                              void* d_out, int out_size)
{
    const float* x     = (const float*)d_in[0];
    const float* W_ih1 = (const float*)d_in[1];
    const float* W_hh1 = (const float*)d_in[2];
    const float* b_ih1 = (const float*)d_in[3];
    const float* b_hh1 = (const float*)d_in[4];
    const float* W_ih2 = (const float*)d_in[5];
    const float* W_hh2 = (const float*)d_in[6];
    const float* b_ih2 = (const float*)d_in[7];
    const float* b_hh2 = (const float*)d_in[8];
    const float* W_lin = (const float*)d_in[9];
    const float* b_lin = (const float*)d_in[10];
    float* out = (float*)d_out;

    const int T = T_FIXED;
    const int B = in_sizes[0] / T;          // 2048
    const int outT = out_size / B;          // T + future = 1088

    // 2 batch elements per warp, 4 warps per block -> 8 batches/block
    const int batchesPerBlock = 8;
    const int nBlocks = (B + batchesPerBlock - 1) / batchesPerBlock;
    lstm2_seq_kernel<<<nBlocks, 128>>>(
        x, W_ih1, W_hh1, b_ih1, b_hh1,
        W_ih2, W_hh2, b_ih2, b_hh2,
        W_lin, b_lin, out, B, T, outT);
}

// round 4
// speedup vs baseline: 1.0362x; 1.0362x over previous
#include <cuda_runtime.h>

// 2-layer LSTM (HID=10) + linear head, B=2048, T=1024, future=64.
// One 16-lane group per batch element; lane j < 10 owns hidden unit j.
// All weights in registers; state broadcast via width-16 shuffles.
// Round 2: fused-reciprocal activations (14 MUFU/step vs 20), layer-2
// partial hoisted into layer-1's activation latency, 2-accumulator dots.

#define HID 10
#define T_FIXED 1024
#define FULLMASK 0xffffffffu

__device__ __forceinline__ float frcp(float x) {
    float r;
    asm("rcp.approx.f32 %0, %1;" : "=f"(r) : "f"(x));
    return r;
}

struct LSTMRegs {
    float wih1[4];        // W_ih1 rows (j,10+j,20+j,30+j), col 0
    float b1[4];          // b_ih1 + b_hh1
    float b2[4];          // b_ih2 + b_hh2
    float whh1[4][HID];
    float wih2[4][HID];
    float whh2[4][HID];
    float wlin;
    float blin;
};

// Fused LSTM cell update: given gates (gi, gf, gg, go) and c, produce h, c'.
//   c' = sigma(gf)*c + sigma(gi)*tanh(gg)
//      = c/(1+u) + (1-w)/((1+v)(1+w)),   u=e^-gf, v=e^-gi, w=e^-2gg
//   h  = sigma(go)*tanh(c') = (1-z)/((1+z)(1+q)),  z=e^-2c', q=e^-go
// 5 EX2 + 2 RCP per layer (vs 10 MUFU for naive per-sigmoid form).
__device__ __forceinline__ float cell_update(
    float gi, float gf, float gg, float go, float& c)
{
    float u = __expf(-gf);
    float v = __expf(-gi);
    float w = __expf(-2.0f * gg);
    float pu = 1.0f + u;
    float pv = 1.0f + v;
    float pw = 1.0f + w;
    float t  = pv * pw;
    float r1 = frcp(pu * t);
    float cn = fmaf(1.0f - w, pu, c * t) * r1;
    c = cn;
    float z = __expf(-2.0f * cn);
    float q = __expf(-go);
    float r2 = frcp((1.0f + z) * (1.0f + q));
    return (1.0f - z) * r2;
}

// One full time step for both layers + linear head.
// Returns y (valid on ALL lanes of the 16-lane group).
__device__ __forceinline__ float lstm2_step(
    float xt, float& h1, float& c1, float& h2, float& c2,
    const LSTMRegs& R, int j)
{
    // ---- layer 1 gate dots (depend on h1_prev, xt) ----
    float g0a = fmaf(R.wih1[0], xt, R.b1[0]), g0b = 0.0f;
    float g1a = fmaf(R.wih1[1], xt, R.b1[1]), g1b = 0.0f;
    float g2a = fmaf(R.wih1[2], xt, R.b1[2]), g2b = 0.0f;
    float g3a = fmaf(R.wih1[3], xt, R.b1[3]), g3b = 0.0f;
#pragma unroll
    for (int m = 0; m < HID; m += 2) {
        float hm0 = __shfl_sync(FULLMASK, h1, m,     16);
        float hm1 = __shfl_sync(FULLMASK, h1, m + 1, 16);
        g0a = fmaf(R.whh1[0][m], hm0, g0a); g0b = fmaf(R.whh1[0][m+1], hm1, g0b);
        g1a = fmaf(R.whh1[1][m], hm0, g1a); g1b = fmaf(R.whh1[1][m+1], hm1, g1b);
        g2a = fmaf(R.whh1[2][m], hm0, g2a); g2b = fmaf(R.whh1[2][m+1], hm1, g2b);
        g3a = fmaf(R.whh1[3][m], hm0, g3a); g3b = fmaf(R.whh1[3][m+1], hm1, g3b);
    }

    // ---- layer 2 partial from h2_prev (independent of layer 1 -> fills
    //      layer-1 activation latency) ----
    float a0a = R.b2[0], a0b = 0.0f;
    float a1a = R.b2[1], a1b = 0.0f;
    float a2a = R.b2[2], a2b = 0.0f;
    float a3a = R.b2[3], a3b = 0.0f;
#pragma unroll
    for (int m = 0; m < HID; m += 2) {
        float hm0 = __shfl_sync(FULLMASK, h2, m,     16);
        float hm1 = __shfl_sync(FULLMASK, h2, m + 1, 16);
        a0a = fmaf(R.whh2[0][m], hm0, a0a); a0b = fmaf(R.whh2[0][m+1], hm1, a0b);
        a1a = fmaf(R.whh2[1][m], hm0, a1a); a1b = fmaf(R.whh2[1][m+1], hm1, a1b);
        a2a = fmaf(R.whh2[2][m], hm0, a2a); a2b = fmaf(R.whh2[2][m+1], hm1, a2b);
        a3a = fmaf(R.whh2[3][m], hm0, a3a); a3b = fmaf(R.whh2[3][m+1], hm1, a3b);
    }

    // ---- layer 1 activations ----
    h1 = cell_update(g0a + g0b, g1a + g1b, g2a + g2b, g3a + g3b, c1);

    // ---- layer 2 finish: += W_ih2 * h1_new ----
#pragma unroll
    for (int m = 0; m < HID; m += 2) {
        float hm0 = __shfl_sync(FULLMASK, h1, m,     16);
        float hm1 = __shfl_sync(FULLMASK, h1, m + 1, 16);
        a0a = fmaf(R.wih2[0][m], hm0, a0a); a0b = fmaf(R.wih2[0][m+1], hm1, a0b);
        a1a = fmaf(R.wih2[1][m], hm0, a1a); a1b = fmaf(R.wih2[1][m+1], hm1, a1b);
        a2a = fmaf(R.wih2[2][m], hm0, a2a); a2b = fmaf(R.wih2[2][m+1], hm1, a2b);
        a3a = fmaf(R.wih2[3][m], hm0, a3a); a3b = fmaf(R.wih2[3][m+1], hm1, a3b);
    }

    // ---- layer 2 activations ----
    h2 = cell_update(a0a + a0b, a1a + a1b, a2a + a2b, a3a + a3b, c2);

    // ---- linear head: y = sum_j wlin[j]*h2[j] + blin over the 16-group ----
    float p = R.wlin * h2;   // wlin is 0 on lanes j >= HID
    p += __shfl_xor_sync(FULLMASK, p, 8, 16);
    p += __shfl_xor_sync(FULLMASK, p, 4, 16);
    p += __shfl_xor_sync(FULLMASK, p, 2, 16);
    p += __shfl_xor_sync(FULLMASK, p, 1, 16);
    return p + R.blin;
}

__global__ void __launch_bounds__(128)
lstm2_seq_kernel(
    const float* __restrict__ x,
    const float* __restrict__ W_ih1, const float* __restrict__ W_hh1,
    const float* __restrict__ b_ih1, const float* __restrict__ b_hh1,
    const float* __restrict__ W_ih2, const float* __restrict__ W_hh2,
    const float* __restrict__ b_ih2, const float* __restrict__ b_hh2,
    const float* __restrict__ W_lin, const float* __restrict__ b_lin,
    float* __restrict__ out,
    int B, int T, int outT)
{
    const int tid    = blockIdx.x * blockDim.x + threadIdx.x;
    const int warpId = tid >> 5;
    const int lane   = tid & 31;
    const int half   = lane >> 4;     // which batch within the warp
    const int j      = lane & 15;     // lane within the 16-lane group
    const int b      = warpId * 2 + half;

    const bool act = (j < HID) && (b < B);

    LSTMRegs R;
#pragma unroll
    for (int g = 0; g < 4; g++) {
        const int r = g * HID + j;    // gate row (only valid when act)
        R.wih1[g] = act ? W_ih1[r] : 0.0f;
        R.b1[g]   = act ? (b_ih1[r] + b_hh1[r]) : 0.0f;
        R.b2[g]   = act ? (b_ih2[r] + b_hh2[r]) : 0.0f;
#pragma unroll
        for (int m = 0; m < HID; m++) {
            R.whh1[g][m] = act ? W_hh1[r * HID + m] : 0.0f;
            R.wih2[g][m] = act ? W_ih2[r * HID + m] : 0.0f;
            R.whh2[g][m] = act ? W_hh2[r * HID + m] : 0.0f;
        }
    }
    R.wlin = act ? W_lin[j] : 0.0f;
    R.blin = b_lin[0];

    float h1 = 0.0f, c1 = 0.0f, h2 = 0.0f, c2 = 0.0f;
    float y = 0.0f, ybuf = 0.0f;

    const bool bvalid = (b < B);
    const float* xrow = x + (size_t)(bvalid ? b : 0) * T;
    float* orow = out + (size_t)(bvalid ? b : 0) * outT;

    // ---- main sequence: T steps, processed in chunks of 16 ----
    for (int t0 = 0; t0 < T; t0 += 16) {
        float xch = bvalid ? xrow[t0 + j] : 0.0f;  // coalesced 16-step chunk
#pragma unroll 1
        for (int tt = 0; tt < 16; tt++) {
            float xt = __shfl_sync(FULLMASK, xch, tt, 16);
            y = lstm2_step(xt, h1, c1, h2, c2, R, j);
            if (j == tt) ybuf = y;
        }
        if (bvalid) orow[t0 + j] = ybuf;           // coalesced store
    }

    // ---- future steps: feed y back as input ----
    for (int t0 = T; t0 < outT; t0 += 16) {
        const int nsteps = min(16, outT - t0);
#pragma unroll 1
        for (int tt = 0; tt < nsteps; tt++) {
            y = lstm2_step(y, h1, c1, h2, c2, R, j);
            if (j == tt) ybuf = y;
        }
        if (bvalid && j < nsteps) orow[t0 + j] = ybuf;
    }
}

extern "C" void kernel_launch(void* const* d_in, const int* in_sizes, int n_in,
                              void* d_out, int out_size)
{
    const float* x     = (const float*)d_in[0];
    const float* W_ih1 = (const float*)d_in[1];
    const float* W_hh1 = (const float*)d_in[2];
    const float* b_ih1 = (const float*)d_in[3];
    const float* b_hh1 = (const float*)d_in[4];
    const float* W_ih2 = (const float*)d_in[5];
    const float* W_hh2 = (const float*)d_in[6];
    const float* b_ih2 = (const float*)d_in[7];
    const float* b_hh2 = (const float*)d_in[8];
    const float* W_lin = (const float*)d_in[9];
    const float* b_lin = (const float*)d_in[10];
    float* out = (float*)d_out;

    const int T = T_FIXED;
    const int B = in_sizes[0] / T;          // 2048
    const int outT = out_size / B;          // T + future = 1088

    // 2 batch elements per warp, 4 warps per block -> 8 batches/block
    const int batchesPerBlock = 8;
    const int nBlocks = (B + batchesPerBlock - 1) / batchesPerBlock;
    lstm2_seq_kernel<<<nBlocks, 128>>>(
        x, W_ih1, W_hh1, b_ih1, b_hh1,
        W_ih2, W_hh2, b_ih2, b_hh2,
        W_lin, b_lin, out, B, T, outT);
}

// round 8
// speedup vs baseline: 1.4609x; 1.4098x over previous
#include <cuda_runtime.h>

// 2-layer LSTM (HID=10) + linear head, B=2048, T=1024, future=64.
// One 16-lane group per batch element; lane j < 10 owns hidden unit j.
// Round 5: f32x2 packed FMAs (fma.rn.f32x2) for all gate dots +
// tanh.approx.f32 HW activations. ~165 warp-instr/step vs ~236.

#define HID 10
#define T_FIXED 1024
#define FULLMASK 0xffffffffu

typedef unsigned long long u64;

__device__ __forceinline__ u64 pack2(float lo, float hi) {
    u64 d; asm("mov.b64 %0, {%1, %2};" : "=l"(d) : "f"(lo), "f"(hi)); return d;
}
__device__ __forceinline__ void unpack2(u64 d, float& lo, float& hi) {
    asm("mov.b64 {%0, %1}, %2;" : "=f"(lo), "=f"(hi) : "l"(d));
}
__device__ __forceinline__ u64 ffma2(u64 a, u64 b, u64 c) {
    u64 d; asm("fma.rn.f32x2 %0, %1, %2, %3;" : "=l"(d) : "l"(a), "l"(b), "l"(c));
    return d;
}
__device__ __forceinline__ float tanh_hw(float v) {
    float r; asm("tanh.approx.f32 %0, %1;" : "=f"(r) : "f"(v)); return r;
}
__device__ __forceinline__ float sig_hw(float v) {
    // sigmoid(v) = 0.5*tanh(0.5v) + 0.5
    return fmaf(tanh_hw(0.5f * v), 0.5f, 0.5f);
}

struct LSTMRegs {
    float wih1[4];        // W_ih1 rows (j,10+j,20+j,30+j), col 0
    float b1[4];          // b_ih1 + b_hh1
    float b2[4];          // b_ih2 + b_hh2
    u64 whh1[4][HID/2];   // packed (m, m+1) weight pairs
    u64 wih2[4][HID/2];
    u64 whh2[4][HID/2];
    float wlin;
    float blin;
};

// Fused cell update with HW tanh.
__device__ __forceinline__ float cell_update(
    float gi, float gf, float gg, float go, float& c)
{
    float si = sig_hw(gi);
    float sf = sig_hw(gf);
    float so = sig_hw(go);
    float tg = tanh_hw(gg);
    c = fmaf(sf, c, si * tg);
    return so * tanh_hw(c);
}

// One full time step for both layers + linear head.
__device__ __forceinline__ float lstm2_step(
    float xt, float& h1, float& c1, float& h2, float& c2,
    const LSTMRegs& R, int j)
{
    // ---- layer 1 gate dots: packed over (m, m+1) halves ----
    u64 g0 = pack2(fmaf(R.wih1[0], xt, R.b1[0]), 0.0f);
    u64 g1 = pack2(fmaf(R.wih1[1], xt, R.b1[1]), 0.0f);
    u64 g2 = pack2(fmaf(R.wih1[2], xt, R.b1[2]), 0.0f);
    u64 g3 = pack2(fmaf(R.wih1[3], xt, R.b1[3]), 0.0f);
#pragma unroll
    for (int m = 0; m < HID; m += 2) {
        float hm0 = __shfl_sync(FULLMASK, h1, m,     16);
        float hm1 = __shfl_sync(FULLMASK, h1, m + 1, 16);
        u64 hp = pack2(hm0, hm1);
        g0 = ffma2(R.whh1[0][m>>1], hp, g0);
        g1 = ffma2(R.whh1[1][m>>1], hp, g1);
        g2 = ffma2(R.whh1[2][m>>1], hp, g2);
        g3 = ffma2(R.whh1[3][m>>1], hp, g3);
    }

    // ---- layer 2 partial from h2_prev (independent of layer 1) ----
    u64 a0 = pack2(R.b2[0], 0.0f);
    u64 a1 = pack2(R.b2[1], 0.0f);
    u64 a2 = pack2(R.b2[2], 0.0f);
    u64 a3 = pack2(R.b2[3], 0.0f);
#pragma unroll
    for (int m = 0; m < HID; m += 2) {
        float hm0 = __shfl_sync(FULLMASK, h2, m,     16);
        float hm1 = __shfl_sync(FULLMASK, h2, m + 1, 16);
        u64 hp = pack2(hm0, hm1);
        a0 = ffma2(R.whh2[0][m>>1], hp, a0);
        a1 = ffma2(R.whh2[1][m>>1], hp, a1);
        a2 = ffma2(R.whh2[2][m>>1], hp, a2);
        a3 = ffma2(R.whh2[3][m>>1], hp, a3);
    }

    // ---- layer 1 activations ----
    {
        float l0, h0_, l1_, h1_, l2_, h2_, l3_, h3_;
        unpack2(g0, l0, h0_);  unpack2(g1, l1_, h1_);
        unpack2(g2, l2_, h2_); unpack2(g3, l3_, h3_);
        h1 = cell_update(l0 + h0_, l1_ + h1_, l2_ + h2_, l3_ + h3_, c1);
    }

    // ---- layer 2 finish: += W_ih2 * h1_new ----
#pragma unroll
    for (int m = 0; m < HID; m += 2) {
        float hm0 = __shfl_sync(FULLMASK, h1, m,     16);
        float hm1 = __shfl_sync(FULLMASK, h1, m + 1, 16);
        u64 hp = pack2(hm0, hm1);
        a0 = ffma2(R.wih2[0][m>>1], hp, a0);
        a1 = ffma2(R.wih2[1][m>>1], hp, a1);
        a2 = ffma2(R.wih2[2][m>>1], hp, a2);
        a3 = ffma2(R.wih2[3][m>>1], hp, a3);
    }

    // ---- layer 2 activations ----
    {
        float l0, h0_, l1_, h1_, l2_, h2_, l3_, h3_;
        unpack2(a0, l0, h0_);  unpack2(a1, l1_, h1_);
        unpack2(a2, l2_, h2_); unpack2(a3, l3_, h3_);
        h2 = cell_update(l0 + h0_, l1_ + h1_, l2_ + h2_, l3_ + h3_, c2);
    }

    // ---- linear head: reduce wlin[j]*h2[j] over the 16-group ----
    float p = R.wlin * h2;   // wlin is 0 on lanes j >= HID
    p += __shfl_xor_sync(FULLMASK, p, 8, 16);
    p += __shfl_xor_sync(FULLMASK, p, 4, 16);
    p += __shfl_xor_sync(FULLMASK, p, 2, 16);
    p += __shfl_xor_sync(FULLMASK, p, 1, 16);
    return p + R.blin;
}

__global__ void __launch_bounds__(256)
lstm2_seq_kernel(
    const float* __restrict__ x,
    const float* __restrict__ W_ih1, const float* __restrict__ W_hh1,
    const float* __restrict__ b_ih1, const float* __restrict__ b_hh1,
    const float* __restrict__ W_ih2, const float* __restrict__ W_hh2,
    const float* __restrict__ b_ih2, const float* __restrict__ b_hh2,
    const float* __restrict__ W_lin, const float* __restrict__ b_lin,
    float* __restrict__ out,
    int B, int T, int outT)
{
    const int tid    = blockIdx.x * blockDim.x + threadIdx.x;
    const int warpId = tid >> 5;
    const int lane   = tid & 31;
    const int half   = lane >> 4;     // which batch within the warp
    const int j      = lane & 15;     // lane within the 16-lane group
    const int b      = warpId * 2 + half;

    const bool act = (j < HID) && (b < B);

    LSTMRegs R;
#pragma unroll
    for (int g = 0; g < 4; g++) {
        const int r = g * HID + j;    // gate row (only valid when act)
        R.wih1[g] = act ? W_ih1[r] : 0.0f;
        R.b1[g]   = act ? (b_ih1[r] + b_hh1[r]) : 0.0f;
        R.b2[g]   = act ? (b_ih2[r] + b_hh2[r]) : 0.0f;
#pragma unroll
        for (int m = 0; m < HID; m += 2) {
            float w0, w1;
            w0 = act ? W_hh1[r * HID + m]     : 0.0f;
            w1 = act ? W_hh1[r * HID + m + 1] : 0.0f;
            R.whh1[g][m>>1] = pack2(w0, w1);
            w0 = act ? W_ih2[r * HID + m]     : 0.0f;
            w1 = act ? W_ih2[r * HID + m + 1] : 0.0f;
            R.wih2[g][m>>1] = pack2(w0, w1);
            w0 = act ? W_hh2[r * HID + m]     : 0.0f;
            w1 = act ? W_hh2[r * HID + m + 1] : 0.0f;
            R.whh2[g][m>>1] = pack2(w0, w1);
        }
    }
    R.wlin = act ? W_lin[j] : 0.0f;
    R.blin = b_lin[0];

    float h1 = 0.0f, c1 = 0.0f, h2 = 0.0f, c2 = 0.0f;
    float y = 0.0f, ybuf = 0.0f;

    const bool bvalid = (b < B);
    const float* xrow = x + (size_t)(bvalid ? b : 0) * T;
    float* orow = out + (size_t)(bvalid ? b : 0) * outT;

    // ---- main sequence: T steps, processed in chunks of 16 ----
    for (int t0 = 0; t0 < T; t0 += 16) {
        float xch = bvalid ? xrow[t0 + j] : 0.0f;  // coalesced 16-step chunk
#pragma unroll 1
        for (int tt = 0; tt < 16; tt++) {
            float xt = __shfl_sync(FULLMASK, xch, tt, 16);
            y = lstm2_step(xt, h1, c1, h2, c2, R, j);
            if (j == tt) ybuf = y;
        }
        if (bvalid) orow[t0 + j] = ybuf;           // coalesced store
    }

    // ---- future steps: feed y back as input ----
    for (int t0 = T; t0 < outT; t0 += 16) {
        const int nsteps = min(16, outT - t0);
#pragma unroll 1
        for (int tt = 0; tt < nsteps; tt++) {
            y = lstm2_step(y, h1, c1, h2, c2, R, j);
            if (j == tt) ybuf = y;
        }
        if (bvalid && j < nsteps) orow[t0 + j] = ybuf;
    }
}

extern "C" void kernel_launch(void* const* d_in, const int* in_sizes, int n_in,
                              void* d_out, int out_size)
{
    const float* x     = (const float*)d_in[0];
    const float* W_ih1 = (const float*)d_in[1];
    const float* W_hh1 = (const float*)d_in[2];
    const float* b_ih1 = (const float*)d_in[3];
    const float* b_hh1 = (const float*)d_in[4];
    const float* W_ih2 = (const float*)d_in[5];
    const float* W_hh2 = (const float*)d_in[6];
    const float* b_ih2 = (const float*)d_in[7];
    const float* b_hh2 = (const float*)d_in[8];
    const float* W_lin = (const float*)d_in[9];
    const float* b_lin = (const float*)d_in[10];
    float* out = (float*)d_out;

    const int T = T_FIXED;
    const int B = in_sizes[0] / T;          // 2048
    const int outT = out_size / B;          // T + future = 1088

    // 2 batches per warp, 8 warps per block -> 16 batches/block.
    // 128 blocks -> every active SM gets a uniform 2 warps/SMSP.
    const int batchesPerBlock = 16;
    const int nBlocks = (B + batchesPerBlock - 1) / batchesPerBlock;
    lstm2_seq_kernel<<<nBlocks, 256>>>(
        x, W_ih1, W_hh1, b_ih1, b_hh1,
        W_ih2, W_hh2, b_ih2, b_hh2,
        W_lin, b_lin, out, B, T, outT);
}

// round 10
// speedup vs baseline: 1.4612x; 1.0003x over previous
#include <cuda_runtime.h>

// 2-layer LSTM (HID=10) + linear head, B=2048, T=1024, future=64.
// One 16-lane group per batch element; lane j < 10 owns hidden unit j.
// Round 9: cross-layer software pipelining — layer-1 gates for step t+1
// are computed in the same h1-broadcast loop as layer-2's input dot for
// step t, collapsing the serial 2-layer chain into one layer's chain and
// removing 10 shuffles/step. FFMA2 packed dots + tanh.approx activations.

#define HID 10
#define T_FIXED 1024
#define FULLMASK 0xffffffffu

typedef unsigned long long u64;

__device__ __forceinline__ u64 pack2(float lo, float hi) {
    u64 d; asm("mov.b64 %0, {%1, %2};" : "=l"(d) : "f"(lo), "f"(hi)); return d;
}
__device__ __forceinline__ void unpack2(u64 d, float& lo, float& hi) {
    asm("mov.b64 {%0, %1}, %2;" : "=f"(lo), "=f"(hi) : "l"(d));
}
__device__ __forceinline__ u64 ffma2(u64 a, u64 b, u64 c) {
    u64 d; asm("fma.rn.f32x2 %0, %1, %2, %3;" : "=l"(d) : "l"(a), "l"(b), "l"(c));
    return d;
}
__device__ __forceinline__ float tanh_hw(float v) {
    float r; asm("tanh.approx.f32 %0, %1;" : "=f"(r) : "f"(v)); return r;
}
__device__ __forceinline__ float sig_hw(float v) {
    // sigmoid(v) = 0.5*tanh(0.5v) + 0.5
    return fmaf(tanh_hw(0.5f * v), 0.5f, 0.5f);
}

struct LSTMRegs {
    float wih1[4];        // W_ih1 rows (j,10+j,20+j,30+j), col 0
    float b1[4];          // b_ih1 + b_hh1
    float b2[4];          // b_ih2 + b_hh2
    u64 whh1[4][HID/2];   // packed (m, m+1) weight pairs
    u64 wih2[4][HID/2];
    u64 whh2[4][HID/2];
    float wlin;
    float blin;
};

// Fused cell update with HW tanh.
__device__ __forceinline__ float cell_update(
    float gi, float gf, float gg, float go, float& c)
{
    float si = sig_hw(gi);
    float sf = sig_hw(gf);
    float so = sig_hw(go);
    float tg = tanh_hw(gg);
    c = fmaf(sf, c, si * tg);
    return so * tanh_hw(c);
}

__device__ __forceinline__ float act_from_packed(
    u64 g0, u64 g1, u64 g2, u64 g3, float& c)
{
    float l0, h0, l1, h1, l2, h2, l3, h3;
    unpack2(g0, l0, h0);  unpack2(g1, l1, h1);
    unpack2(g2, l2, h2);  unpack2(g3, l3, h3);
    return cell_update(l0 + h0, l1 + h1, l2 + h2, l3 + h3, c);
}

// Full sequential step (used for the last main step + 64 future steps).
__device__ __forceinline__ float lstm2_step(
    float xt, float& h1, float& c1, float& h2, float& c2,
    const LSTMRegs& R, int j)
{
    u64 g0 = pack2(fmaf(R.wih1[0], xt, R.b1[0]), 0.0f);
    u64 g1 = pack2(fmaf(R.wih1[1], xt, R.b1[1]), 0.0f);
    u64 g2 = pack2(fmaf(R.wih1[2], xt, R.b1[2]), 0.0f);
    u64 g3 = pack2(fmaf(R.wih1[3], xt, R.b1[3]), 0.0f);
#pragma unroll
    for (int m = 0; m < HID; m += 2) {
        float hm0 = __shfl_sync(FULLMASK, h1, m,     16);
        float hm1 = __shfl_sync(FULLMASK, h1, m + 1, 16);
        u64 hp = pack2(hm0, hm1);
        g0 = ffma2(R.whh1[0][m>>1], hp, g0);
        g1 = ffma2(R.whh1[1][m>>1], hp, g1);
        g2 = ffma2(R.whh1[2][m>>1], hp, g2);
        g3 = ffma2(R.whh1[3][m>>1], hp, g3);
    }

    u64 a0 = pack2(R.b2[0], 0.0f);
    u64 a1 = pack2(R.b2[1], 0.0f);
    u64 a2 = pack2(R.b2[2], 0.0f);
    u64 a3 = pack2(R.b2[3], 0.0f);
#pragma unroll
    for (int m = 0; m < HID; m += 2) {
        float hm0 = __shfl_sync(FULLMASK, h2, m,     16);
        float hm1 = __shfl_sync(FULLMASK, h2, m + 1, 16);
        u64 hp = pack2(hm0, hm1);
        a0 = ffma2(R.whh2[0][m>>1], hp, a0);
        a1 = ffma2(R.whh2[1][m>>1], hp, a1);
        a2 = ffma2(R.whh2[2][m>>1], hp, a2);
        a3 = ffma2(R.whh2[3][m>>1], hp, a3);
    }

    h1 = act_from_packed(g0, g1, g2, g3, c1);

#pragma unroll
    for (int m = 0; m < HID; m += 2) {
        float hm0 = __shfl_sync(FULLMASK, h1, m,     16);
        float hm1 = __shfl_sync(FULLMASK, h1, m + 1, 16);
        u64 hp = pack2(hm0, hm1);
        a0 = ffma2(R.wih2[0][m>>1], hp, a0);
        a1 = ffma2(R.wih2[1][m>>1], hp, a1);
        a2 = ffma2(R.wih2[2][m>>1], hp, a2);
        a3 = ffma2(R.wih2[3][m>>1], hp, a3);
    }

    h2 = act_from_packed(a0, a1, a2, a3, c2);

    float p = R.wlin * h2;   // wlin is 0 on lanes j >= HID
    p += __shfl_xor_sync(FULLMASK, p, 8, 16);
    p += __shfl_xor_sync(FULLMASK, p, 4, 16);
    p += __shfl_xor_sync(FULLMASK, p, 2, 16);
    p += __shfl_xor_sync(FULLMASK, p, 1, 16);
    return p + R.blin;
}

__global__ void __launch_bounds__(256)
lstm2_seq_kernel(
    const float* __restrict__ x,
    const float* __restrict__ W_ih1, const float* __restrict__ W_hh1,
    const float* __restrict__ b_ih1, const float* __restrict__ b_hh1,
    const float* __restrict__ W_ih2, const float* __restrict__ W_hh2,
    const float* __restrict__ b_ih2, const float* __restrict__ b_hh2,
    const float* __restrict__ W_lin, const float* __restrict__ b_lin,
    float* __restrict__ out,
    int B, int T, int outT)
{
    const int tid    = blockIdx.x * blockDim.x + threadIdx.x;
    const int warpId = tid >> 5;
    const int lane   = tid & 31;
    const int half   = lane >> 4;     // which batch within the warp
    const int j      = lane & 15;     // lane within the 16-lane group
    const int b      = warpId * 2 + half;

    const bool act = (j < HID) && (b < B);

    LSTMRegs R;
#pragma unroll
    for (int g = 0; g < 4; g++) {
        const int r = g * HID + j;    // gate row (only valid when act)
        R.wih1[g] = act ? W_ih1[r] : 0.0f;
        R.b1[g]   = act ? (b_ih1[r] + b_hh1[r]) : 0.0f;
        R.b2[g]   = act ? (b_ih2[r] + b_hh2[r]) : 0.0f;
#pragma unroll
        for (int m = 0; m < HID; m += 2) {
            float w0, w1;
            w0 = act ? W_hh1[r * HID + m]     : 0.0f;
            w1 = act ? W_hh1[r * HID + m + 1] : 0.0f;
            R.whh1[g][m>>1] = pack2(w0, w1);
            w0 = act ? W_ih2[r * HID + m]     : 0.0f;
            w1 = act ? W_ih2[r * HID + m + 1] : 0.0f;
            R.wih2[g][m>>1] = pack2(w0, w1);
            w0 = act ? W_hh2[r * HID + m]     : 0.0f;
            w1 = act ? W_hh2[r * HID + m + 1] : 0.0f;
            R.whh2[g][m>>1] = pack2(w0, w1);
        }
    }
    R.wlin = act ? W_lin[j] : 0.0f;
    R.blin = b_lin[0];

    float h1 = 0.0f, c1 = 0.0f, h2 = 0.0f, c2 = 0.0f;
    float y = 0.0f, ybuf = 0.0f;

    const bool bvalid = (b < B);
    const float* xrow = x + (size_t)(bvalid ? b : 0) * T;
    float* orow = out + (size_t)(bvalid ? b : 0) * outT;

    // ---- prologue: chunk 0 and gates for step 0 (h1 init is zero) ----
    float chunk = bvalid ? xrow[j] : 0.0f;           // x[0..15]
    float x0 = __shfl_sync(FULLMASK, chunk, 0, 16);
    u64 G0 = pack2(fmaf(R.wih1[0], x0, R.b1[0]), 0.0f);
    u64 G1 = pack2(fmaf(R.wih1[1], x0, R.b1[1]), 0.0f);
    u64 G2 = pack2(fmaf(R.wih1[2], x0, R.b1[2]), 0.0f);
    u64 G3 = pack2(fmaf(R.wih1[3], x0, R.b1[3]), 0.0f);

    // ---- pipelined main loop: steps 0 .. T-2 ----
#pragma unroll 1
    for (int t = 0; t < T - 1; t++) {
        // layer-1 activation for step t (consumes G)
        h1 = act_from_packed(G0, G1, G2, G3, c1);

        // next input x(t+1); refill chunk every 16 steps
        if (((t + 1) & 15) == 0)
            chunk = bvalid ? xrow[t + 1 + j] : 0.0f;
        float xt1 = __shfl_sync(FULLMASK, chunk, (t + 1) & 15, 16);

        // layer-2 partial from h2(t-1)
        u64 A0 = pack2(R.b2[0], 0.0f);
        u64 A1 = pack2(R.b2[1], 0.0f);
        u64 A2 = pack2(R.b2[2], 0.0f);
        u64 A3 = pack2(R.b2[3], 0.0f);
#pragma unroll
        for (int m = 0; m < HID; m += 2) {
            float hm0 = __shfl_sync(FULLMASK, h2, m,     16);
            float hm1 = __shfl_sync(FULLMASK, h2, m + 1, 16);
            u64 hp = pack2(hm0, hm1);
            A0 = ffma2(R.whh2[0][m>>1], hp, A0);
            A1 = ffma2(R.whh2[1][m>>1], hp, A1);
            A2 = ffma2(R.whh2[2][m>>1], hp, A2);
            A3 = ffma2(R.whh2[3][m>>1], hp, A3);
        }

        // gates for step t+1 (layer 1)
        u64 N0 = pack2(fmaf(R.wih1[0], xt1, R.b1[0]), 0.0f);
        u64 N1 = pack2(fmaf(R.wih1[1], xt1, R.b1[1]), 0.0f);
        u64 N2 = pack2(fmaf(R.wih1[2], xt1, R.b1[2]), 0.0f);
        u64 N3 = pack2(fmaf(R.wih1[3], xt1, R.b1[3]), 0.0f);

        // shared h1(t) broadcast: feeds BOTH layer-2 input dot (step t)
        // and layer-1 recurrent dot (step t+1)
#pragma unroll
        for (int m = 0; m < HID; m += 2) {
            float hm0 = __shfl_sync(FULLMASK, h1, m,     16);
            float hm1 = __shfl_sync(FULLMASK, h1, m + 1, 16);
            u64 hp = pack2(hm0, hm1);
            A0 = ffma2(R.wih2[0][m>>1], hp, A0);
            A1 = ffma2(R.wih2[1][m>>1], hp, A1);
            A2 = ffma2(R.wih2[2][m>>1], hp, A2);
            A3 = ffma2(R.wih2[3][m>>1], hp, A3);
            N0 = ffma2(R.whh1[0][m>>1], hp, N0);
            N1 = ffma2(R.whh1[1][m>>1], hp, N1);
            N2 = ffma2(R.whh1[2][m>>1], hp, N2);
            N3 = ffma2(R.whh1[3][m>>1], hp, N3);
        }
        G0 = N0; G1 = N1; G2 = N2; G3 = N3;

        // layer-2 activation + head for step t
        h2 = act_from_packed(A0, A1, A2, A3, c2);

        float p = R.wlin * h2;
        p += __shfl_xor_sync(FULLMASK, p, 8, 16);
        p += __shfl_xor_sync(FULLMASK, p, 4, 16);
        p += __shfl_xor_sync(FULLMASK, p, 2, 16);
        p += __shfl_xor_sync(FULLMASK, p, 1, 16);
        y = p + R.blin;

        if (j == (t & 15)) ybuf = y;
        if ((t & 15) == 15 && bvalid) orow[(t & ~15) + j] = ybuf;
    }

    // ---- tail: step T-1 (input x[T-1]) + future steps (y feedback) ----
    float xt = __shfl_sync(FULLMASK, chunk, 15, 16);  // x[T-1]
#pragma unroll 1
    for (int t = T - 1; t < outT; t++) {
        y = lstm2_step(xt, h1, c1, h2, c2, R, j);
        xt = y;
        if (j == (t & 15)) ybuf = y;
        if ((t & 15) == 15 && bvalid) orow[(t & ~15) + j] = ybuf;
    }
}

extern "C" void kernel_launch(void* const* d_in, const int* in_sizes, int n_in,
                              void* d_out, int out_size)
{
    const float* x     = (const float*)d_in[0];
    const float* W_ih1 = (const float*)d_in[1];
    const float* W_hh1 = (const float*)d_in[2];
    const float* b_ih1 = (const float*)d_in[3];
    const float* b_hh1 = (const float*)d_in[4];
    const float* W_ih2 = (const float*)d_in[5];
    const float* W_hh2 = (const float*)d_in[6];
    const float* b_ih2 = (const float*)d_in[7];
    const float* b_hh2 = (const float*)d_in[8];
    const float* W_lin = (const float*)d_in[9];
    const float* b_lin = (const float*)d_in[10];
    float* out = (float*)d_out;

    const int T = T_FIXED;
    const int B = in_sizes[0] / T;          // 2048
    const int outT = out_size / B;          // T + future = 1088

    // 2 batches per warp, 8 warps per block -> 16 batches/block.
    const int batchesPerBlock = 16;
    const int nBlocks = (B + batchesPerBlock - 1) / batchesPerBlock;
    lstm2_seq_kernel<<<nBlocks, 256>>>(
        x, W_ih1, W_hh1, b_ih1, b_hh1,
        W_ih2, W_hh2, b_ih2, b_hh2,
        W_lin, b_lin, out, B, T, outT);
}

// round 11
// speedup vs baseline: 1.6612x; 1.1368x over previous
#include <cuda_runtime.h>

// 2-layer LSTM (HID=10) + linear head, B=2048, T=1024, future=64.
// Round 11: dense lane mapping — 10-lane groups, 3 batches/warp (30/32
// lanes active vs 20/32), smem broadcast instead of shuffles, deferred
// head, staged x/y. Rationale: workload is fma-pipe rt-bound per SMSP;
// fewer fma warp-instructions per batch is the only lever.

#define HID 10
#define T_FIXED 1024

typedef unsigned long long u64;

__device__ __forceinline__ u64 pack2(float lo, float hi) {
    u64 d; asm("mov.b64 %0, {%1, %2};" : "=l"(d) : "f"(lo), "f"(hi)); return d;
}
__device__ __forceinline__ void unpack2(u64 d, float& lo, float& hi) {
    asm("mov.b64 {%0, %1}, %2;" : "=f"(lo), "=f"(hi) : "l"(d));
}
__device__ __forceinline__ u64 ffma2(u64 a, u64 b, u64 c) {
    u64 d; asm("fma.rn.f32x2 %0, %1, %2, %3;" : "=l"(d) : "l"(a), "l"(b), "l"(c));
    return d;
}
__device__ __forceinline__ float psum(u64 a) {
    float l, h; unpack2(a, l, h); return l + h;
}
__device__ __forceinline__ float tanh_hw(float v) {
    float r; asm("tanh.approx.f32 %0, %1;" : "=f"(r) : "f"(v)); return r;
}
__device__ __forceinline__ float sig_hw(float v) {
    return fmaf(tanh_hw(0.5f * v), 0.5f, 0.5f);
}
__device__ __forceinline__ float cell_update(
    float gi, float gf, float gg, float go, float& c)
{
    float si = sig_hw(gi), sf = sig_hw(gf), so = sig_hw(go), tg = tanh_hw(gg);
    c = fmaf(sf, c, si * tg);
    return so * tanh_hw(c);
}

// Load 10 floats (5 packed f32x2 pairs) from 16B-aligned smem.
// asm volatile + memory clobber: guarantees reload after same-warp STS.
__device__ __forceinline__ void load_vec10(const float* p, u64* v) {
    unsigned a = (unsigned)__cvta_generic_to_shared(p);
    asm volatile("ld.shared.v2.b64 {%0,%1}, [%2];"
                 : "=l"(v[0]), "=l"(v[1]) : "r"(a) : "memory");
    asm volatile("ld.shared.v2.b64 {%0,%1}, [%2];"
                 : "=l"(v[2]), "=l"(v[3]) : "r"(a + 16) : "memory");
    asm volatile("ld.shared.b64 %0, [%1];"
                 : "=l"(v[4]) : "r"(a + 32) : "memory");
}

// Per-warp smem layout (floats): h1v[3][12] | h2v[3][12] | x[3][20] | y[3][20]
#define SW_H1 0
#define SW_H2 36
#define SW_X  72
#define SW_Y  132
#define SW_WARP 192

__global__ void __launch_bounds__(128, 1)
lstm2_seq_kernel(
    const float* __restrict__ x,
    const float* __restrict__ W_ih1, const float* __restrict__ W_hh1,
    const float* __restrict__ b_ih1, const float* __restrict__ b_hh1,
    const float* __restrict__ W_ih2, const float* __restrict__ W_hh2,
    const float* __restrict__ b_ih2, const float* __restrict__ b_hh2,
    const float* __restrict__ W_lin, const float* __restrict__ b_lin,
    float* __restrict__ out,
    int B, int T, int outT)
{
    __shared__ __align__(16) float sm[4 * SW_WARP];

    const int lane    = threadIdx.x & 31;
    const int warpIn  = threadIdx.x >> 5;
    const int warpGl  = blockIdx.x * 4 + warpIn;
    const int g       = lane / 10;          // 0..2 active groups; 3 = idle lanes
    const int k       = lane - g * 10;      // unit index within group
    const int gc      = (g < 3) ? g : 0;
    const int warpB0  = warpGl * 3;
    const int b       = warpB0 + gc;
    const bool alane  = (g < 3) && (b < B);
    float* sw = sm + warpIn * SW_WARP;

    // ---- per-lane weights (registers) ----
    float wih1[4], b1[4], b2[4];
    u64 whh1[4][5], wih2[4][5], whh2[4][5], wlinp[5];
#pragma unroll
    for (int q = 0; q < 4; q++) {
        const int r = q * HID + k;
        wih1[q] = alane ? W_ih1[r] : 0.0f;
        b1[q]   = alane ? (b_ih1[r] + b_hh1[r]) : 0.0f;
        b2[q]   = alane ? (b_ih2[r] + b_hh2[r]) : 0.0f;
#pragma unroll
        for (int p = 0; p < 5; p++) {
            whh1[q][p] = pack2(alane ? W_hh1[r*HID+2*p] : 0.0f,
                               alane ? W_hh1[r*HID+2*p+1] : 0.0f);
            wih2[q][p] = pack2(alane ? W_ih2[r*HID+2*p] : 0.0f,
                               alane ? W_ih2[r*HID+2*p+1] : 0.0f);
            whh2[q][p] = pack2(alane ? W_hh2[r*HID+2*p] : 0.0f,
                               alane ? W_hh2[r*HID+2*p+1] : 0.0f);
        }
    }
#pragma unroll
    for (int p = 0; p < 5; p++) wlinp[p] = pack2(W_lin[2*p], W_lin[2*p+1]);
    const float blin = b_lin[0];

    // zero h vectors (per-warp private; same-warp ordering only)
    for (int i = lane; i < 72; i += 32) sw[i] = 0.0f;

    float c1 = 0.0f, c2 = 0.0f;

    // ---- x chunk staging: load chunk t0 into regs (2 rounds: 32 + 16) ----
    float xr0 = 0.0f, xr1 = 0.0f;
    auto ldg_chunk = [&](int t0, float& r0, float& r1) {
        int i0 = lane;            // 0..31
        int g0_ = i0 >> 4, c0_ = i0 & 15;
        int bb0 = warpB0 + g0_;
        r0 = (bb0 < B) ? x[(size_t)bb0 * T + t0 + c0_] : 0.0f;
        int i1 = 32 + lane;       // 32..47 valid for lane<16
        int bb1 = warpB0 + 2;
        r1 = (lane < 16 && bb1 < B) ? x[(size_t)bb1 * T + t0 + (i1 & 15)] : 0.0f;
    };
    auto sts_chunk = [&](float r0, float r1) {
        int i0 = lane;
        sw[SW_X + (i0 >> 4) * 20 + (i0 & 15)] = r0;
        if (lane < 16) sw[SW_X + 2 * 20 + lane] = r1;
    };
    auto flush_y = [&](int t0) {
#pragma unroll
        for (int r2 = 0; r2 < 2; r2++) {
            int idx = lane + r2 * 32;
            if (idx < 48) {
                int gg = idx >> 4, ii = idx & 15;
                int bb = warpB0 + gg;
                if (bb < B) out[(size_t)bb * outT + t0 + ii] = sw[SW_Y + gg*20 + ii];
            }
        }
    };

    // prologue: commit chunk 0, prefetch chunk 16
    { float a0, a1; ldg_chunk(0, a0, a1); sts_chunk(a0, a1); }
    if (T > 16) ldg_chunk(16, xr0, xr1);

    // gates for step 0 (h1(-1) = 0)
    float x0 = sw[SW_X + gc * 20 + 0];
    u64 G0 = pack2(fmaf(wih1[0], x0, b1[0]), 0.0f);
    u64 G1 = pack2(fmaf(wih1[1], x0, b1[1]), 0.0f);
    u64 G2 = pack2(fmaf(wih1[2], x0, b1[2]), 0.0f);
    u64 G3 = pack2(fmaf(wih1[3], x0, b1[3]), 0.0f);

    // ---- pipelined main loop: steps 0 .. T-2 ----
#pragma unroll 1
    for (int t = 0; t < T - 1; t++) {
        // layer-1 activation for step t
        float h1 = cell_update(psum(G0), psum(G1), psum(G2), psum(G3), c1);
        if (alane) sw[SW_H1 + gc * 12 + k] = h1;

        // h2(t-1) vector
        u64 v[5];
        load_vec10(sw + SW_H2 + gc * 12, v);

        // A = b2 + Whh2 . h2(t-1)
        u64 A0 = pack2(b2[0], 0.0f), A1 = pack2(b2[1], 0.0f);
        u64 A2 = pack2(b2[2], 0.0f), A3 = pack2(b2[3], 0.0f);
#pragma unroll
        for (int p = 0; p < 5; p++) {
            A0 = ffma2(whh2[0][p], v[p], A0);
            A1 = ffma2(whh2[1][p], v[p], A1);
            A2 = ffma2(whh2[2][p], v[p], A2);
            A3 = ffma2(whh2[3][p], v[p], A3);
        }

        // deferred head: y(t-1) = wlin . h2(t-1) + blin
        u64 Y = pack2(0.0f, 0.0f);
#pragma unroll
        for (int p = 0; p < 5; p++) Y = ffma2(wlinp[p], v[p], Y);
        float yprev = psum(Y) + blin;
        if (alane && k == 0) sw[SW_Y + gc * 20 + ((t - 1) & 15)] = yprev;

        // x(t+1): commit prefetched chunk at boundaries, prefetch next
        int tn = t + 1;
        if ((tn & 15) == 0) {
            sts_chunk(xr0, xr1);
            int t0n = tn + 16;
            if (t0n < T) ldg_chunk(t0n, xr0, xr1);
        }
        float xt1 = sw[SW_X + gc * 20 + (tn & 15)];

        // gates for step t+1 (layer 1) init
        u64 N0 = pack2(fmaf(wih1[0], xt1, b1[0]), 0.0f);
        u64 N1 = pack2(fmaf(wih1[1], xt1, b1[1]), 0.0f);
        u64 N2 = pack2(fmaf(wih1[2], xt1, b1[2]), 0.0f);
        u64 N3 = pack2(fmaf(wih1[3], xt1, b1[3]), 0.0f);

        // shared h1(t) vector: feeds ih2 (step t) and hh1 (step t+1)
        u64 w[5];
        load_vec10(sw + SW_H1 + gc * 12, w);
#pragma unroll
        for (int p = 0; p < 5; p++) {
            A0 = ffma2(wih2[0][p], w[p], A0);
            A1 = ffma2(wih2[1][p], w[p], A1);
            A2 = ffma2(wih2[2][p], w[p], A2);
            A3 = ffma2(wih2[3][p], w[p], A3);
            N0 = ffma2(whh1[0][p], w[p], N0);
            N1 = ffma2(whh1[1][p], w[p], N1);
            N2 = ffma2(whh1[2][p], w[p], N2);
            N3 = ffma2(whh1[3][p], w[p], N3);
        }

        // layer-2 activation for step t
        float h2 = cell_update(psum(A0), psum(A1), psum(A2), psum(A3), c2);
        if (alane) sw[SW_H2 + gc * 12 + k] = h2;

        G0 = N0; G1 = N1; G2 = N2; G3 = N3;

        // flush y block [t-16, t-1] once it is complete
        if ((t & 15) == 0 && t > 0) flush_y(t - 16);
    }

    // ---- y(T-2) from h2(T-2) (still pending from deferral) ----
    {
        u64 v[5];
        load_vec10(sw + SW_H2 + gc * 12, v);
        u64 Y = pack2(0.0f, 0.0f);
#pragma unroll
        for (int p = 0; p < 5; p++) Y = ffma2(wlinp[p], v[p], Y);
        float yv = psum(Y) + blin;
        if (alane && k == 0) sw[SW_Y + gc * 20 + ((T - 2) & 15)] = yv;
    }

    // ---- tail: step T-1 with x[T-1], then future steps with y feedback ----
    float xt = sw[SW_X + gc * 20 + 15];   // x[T-1]
#pragma unroll 1
    for (int t = T - 1; t < outT; t++) {
        u64 w[5], v[5];

        // layer 1
        load_vec10(sw + SW_H1 + gc * 12, w);     // h1(t-1)
        u64 g0 = pack2(fmaf(wih1[0], xt, b1[0]), 0.0f);
        u64 g1 = pack2(fmaf(wih1[1], xt, b1[1]), 0.0f);
        u64 g2 = pack2(fmaf(wih1[2], xt, b1[2]), 0.0f);
        u64 g3 = pack2(fmaf(wih1[3], xt, b1[3]), 0.0f);
#pragma unroll
        for (int p = 0; p < 5; p++) {
            g0 = ffma2(whh1[0][p], w[p], g0);
            g1 = ffma2(whh1[1][p], w[p], g1);
            g2 = ffma2(whh1[2][p], w[p], g2);
            g3 = ffma2(whh1[3][p], w[p], g3);
        }
        float h1 = cell_update(psum(g0), psum(g1), psum(g2), psum(g3), c1);
        if (alane) sw[SW_H1 + gc * 12 + k] = h1;

        // layer 2
        load_vec10(sw + SW_H1 + gc * 12, w);     // h1(t)
        load_vec10(sw + SW_H2 + gc * 12, v);     // h2(t-1)
        u64 a0 = pack2(b2[0], 0.0f), a1 = pack2(b2[1], 0.0f);
        u64 a2 = pack2(b2[2], 0.0f), a3 = pack2(b2[3], 0.0f);
#pragma unroll
        for (int p = 0; p < 5; p++) {
            a0 = ffma2(wih2[0][p], w[p], a0);  a0 = ffma2(whh2[0][p], v[p], a0);
            a1 = ffma2(wih2[1][p], w[p], a1);  a1 = ffma2(whh2[1][p], v[p], a1);
            a2 = ffma2(wih2[2][p], w[p], a2);  a2 = ffma2(whh2[2][p], v[p], a2);
            a3 = ffma2(wih2[3][p], w[p], a3);  a3 = ffma2(whh2[3][p], v[p], a3);
        }
        float h2 = cell_update(psum(a0), psum(a1), psum(a2), psum(a3), c2);
        if (alane) sw[SW_H2 + gc * 12 + k] = h2;

        // head from fresh h2(t)
        load_vec10(sw + SW_H2 + gc * 12, v);
        u64 Y = pack2(0.0f, 0.0f);
#pragma unroll
        for (int p = 0; p < 5; p++) Y = ffma2(wlinp[p], v[p], Y);
        float y = psum(Y) + blin;
        if (alane && k == 0) sw[SW_Y + gc * 20 + (t & 15)] = y;
        xt = y;

        if ((t & 15) == 15) flush_y(t & ~15);
    }
}

extern "C" void kernel_launch(void* const* d_in, const int* in_sizes, int n_in,
                              void* d_out, int out_size)
{
    const float* x     = (const float*)d_in[0];
    const float* W_ih1 = (const float*)d_in[1];
    const float* W_hh1 = (const float*)d_in[2];
    const float* b_ih1 = (const float*)d_in[3];
    const float* b_hh1 = (const float*)d_in[4];
    const float* W_ih2 = (const float*)d_in[5];
    const float* W_hh2 = (const float*)d_in[6];
    const float* b_ih2 = (const float*)d_in[7];
    const float* b_hh2 = (const float*)d_in[8];
    const float* W_lin = (const float*)d_in[9];
    const float* b_lin = (const float*)d_in[10];
    float* out = (float*)d_out;

    const int T = T_FIXED;
    const int B = in_sizes[0] / T;          // 2048
    const int outT = out_size / B;          // T + future = 1088

    // 3 batches per warp, 4 warps per block -> 12 batches/block
    const int nWarps  = (B + 2) / 3;                    // 683
    const int nBlocks = (nWarps + 3) / 4;               // 171
    lstm2_seq_kernel<<<nBlocks, 128>>>(
        x, W_ih1, W_hh1, b_ih1, b_hh1,
        W_ih2, W_hh2, b_ih2, b_hh2,
        W_lin, b_lin, out, B, T, outT);
}